// round 2
// baseline (speedup 1.0000x reference)
#include <cuda_runtime.h>

// ---------------------------------------------------------------------------
// Caps2dMatwo fused kernel.
// Shapes: N=2, T0=4 (c), T1=8 (t), H=W=128, PD=AD=4, Z=32, KS=3, ROUTINGS=3.
//
// Key derivation (matches the reference's reshape mixing exactly):
//   conv out u[c, t1', z']  (t1' in 0..7, z' in 0..31)
//   u_pos_val(c,t,i,j) = u[c, t/2,     16*(t&1) + i*4 + j]
//   u_app_val(c,t,i,j) = u[c, 4 + t/2, 16*(t&1) + i*4 + j]
//   mpos[c,t,j,k] = Wp_flat[c*128 + t*16 + j*4 + k], column-normalized over j
//   u_hat[z=i*4+k,    c,t] = sum_j u_pos*mposn + u_pos(j=3)*(k==0? w/W : k==1? h/H : 0)
//   u_hat[z=16+i*4+k, c,t] = b_app[c,t]*sum_j mapp[j,k] + sum_j u_app*mapp[j,k]
// Routing decomposes per (pixel, t): p[z]=sum_c uhat*r[c]; psquash (z<16) /
// matwo (z>=16); rout[c]= (sum_{z<16} uhat*v)*(sum_{z>=16} uhat*v); b+=rout.
// ---------------------------------------------------------------------------

#define SX_SIZE   (4*32*3*36)          // 13824 floats: x tile [c][z][3][36]
#define UH_STRIDE 1033                 // 32 z * 32 ct + 9 pad (odd*? -> 9 mod 32)
#define UH_SIZE   (32*UH_STRIDE)       // 33056 floats
#define SMEM_FLOATS (SX_SIZE + UH_SIZE + 288 + 512 + 512 + 128 + 512*5)
#define SMEM_BYTES (SMEM_FLOATS * 4)   // 203,520 bytes

__device__ __forceinline__ float sigf(float v) {
    return 1.0f / (1.0f + __expf(-v));
}

__global__ void __launch_bounds__(512, 1)
caps_kernel(const float* __restrict__ x,     // (2,4,32,128,128)
            const float* __restrict__ Wc,    // (4,3,3,1,8)  flat 288
            const float* __restrict__ Wp,    // (4,16,8)     flat 512
            const float* __restrict__ Wa,    // (4,16,8)     flat 512
            const float* __restrict__ ba,    // (4,8)        flat 32
            float* __restrict__ out)         // (2,8,32,128,128)
{
    extern __shared__ float sm[];
    float* s_x  = sm;                    // 13824
    float* s_uh = s_x + SX_SIZE;         // 33056, [pix]*1033 + z*32 + ct
    float* s_wc = s_uh + UH_SIZE;        // 288  [c][kh*3+kw][t1]
    float* s_mp = s_wc + 288;            // 512  [c][t][j][k] normalized
    float* s_ma = s_mp + 512;            // 512  [c][t][j][k]
    float* s_bb = s_ma + 512;            // 128  [c][t][k]  = b_app*sum_j mapp
    float* s_ex = s_bb + 128;            // 2560 exchange [tid][5-pad]

    const int tid = threadIdx.x;
    const int w0  = blockIdx.x * 32;
    const int h   = blockIdx.y;
    const int n   = blockIdx.z;

    // ---- weights into smem ----
    if (tid < 288) s_wc[tid] = Wc[tid];
    if (tid < 512) s_ma[tid] = Wa[tid];
    if (tid >= 288 && tid < 416) {
        int q = tid - 288;                       // one (c,t,k) each
        int c = q >> 5, t = (q >> 2) & 7, k = q & 3;
        const float* wpp = Wp + c*128 + t*16 + k;
        float m0 = wpp[0], m1 = wpp[4], m2 = wpp[8], m3 = wpp[12];
        float inv = rsqrtf(fmaxf(m0*m0 + m1*m1 + m2*m2 + m3*m3, 1e-12f));
        float* d = s_mp + (c*8 + t)*16 + k;
        d[0] = m0*inv; d[4] = m1*inv; d[8] = m2*inv; d[12] = m3*inv;
        const float* wap = Wa + c*128 + t*16 + k;
        s_bb[(c*8 + t)*4 + k] = ba[c*8 + t] * (wap[0] + wap[4] + wap[8] + wap[12]);
    }

    // ---- x halo tile load (rows h-1..h+1, cols w0-1..w0+32, zero-padded) ----
    for (int idx = tid; idx < 4*32*3*34; idx += 512) {
        int col  = idx % 34;
        int rest = idx / 34;
        int r3   = rest % 3;
        int cz   = rest / 3;                      // c*32+z
        int gr = h + r3 - 1;
        int gc = w0 + col - 1;
        float v = 0.0f;
        if (gr >= 0 && gr < 128 && gc >= 0 && gc < 128)
            v = x[(((long)n*128 + cz)*128 + gr)*128 + gc];
        s_x[(cz*3 + r3)*36 + col] = v;
    }
    __syncthreads();

    // ---- Phase B: conv + u_hat, 2 units per thread, unit = ct*32 + pix ----
#pragma unroll
    for (int uu = 0; uu < 2; ++uu) {
        int unit = tid + uu*512;
        int ct  = unit >> 5;                      // warp-uniform
        int pix = unit & 31;
        int c = ct >> 3, t = ct & 7;
        int zb  = (t & 1) << 4;
        int t1p = t >> 1;                         // pos channel; app = t1p+4

        float wp9[9], wa9[9];
#pragma unroll
        for (int p = 0; p < 9; ++p) {
            wp9[p] = s_wc[(c*9 + p)*8 + t1p];
            wa9[p] = s_wc[(c*9 + p)*8 + t1p + 4];
        }
        float cp[16], ca[16];
#pragma unroll
        for (int m = 0; m < 16; ++m) {
            const float* xb = s_x + ((c*32 + zb + m)*3)*36 + pix;
            float ap = 0.f, aa = 0.f;
#pragma unroll
            for (int kh = 0; kh < 3; ++kh)
#pragma unroll
                for (int kw = 0; kw < 3; ++kw) {
                    float xv = xb[kh*36 + kw];
                    ap = fmaf(xv, wp9[kh*3 + kw], ap);
                    aa = fmaf(xv, wa9[kh*3 + kw], aa);
                }
            cp[m] = ap; ca[m] = aa;
        }

        float wcd = (float)(w0 + pix) * (1.0f/128.0f);
        float hcd = (float)h * (1.0f/128.0f);
        float* ub = s_uh + pix*UH_STRIDE + ct;
        const float* mp = s_mp + (c*8 + t)*16;
        const float* ma = s_ma + (c*8 + t)*16;
        const float* bb = s_bb + (c*8 + t)*4;
#pragma unroll
        for (int i = 0; i < 4; ++i) {
            float p0 = cp[4*i+0], p1 = cp[4*i+1], p2 = cp[4*i+2], p3 = cp[4*i+3];
            float a0 = ca[4*i+0], a1 = ca[4*i+1], a2 = ca[4*i+2], a3 = ca[4*i+3];
#pragma unroll
            for (int k = 0; k < 4; ++k) {
                float u = p0*mp[k] + p1*mp[4+k] + p2*mp[8+k] + p3*mp[12+k];
                if (k == 0) u += p3 * wcd;
                if (k == 1) u += p3 * hcd;
                ub[(i*4 + k)*32] = u;
                float va = bb[k] + a0*ma[k] + a1*ma[4+k] + a2*ma[8+k] + a3*ma[12+k];
                ub[(16 + i*4 + k)*32] = va;
            }
        }
    }
    __syncthreads();

    // ---- Phase C: routing, thread = (s=pos/app, t, pix) ----
    {
        const int s   = tid >> 8;                 // warp-uniform
        const int t   = (tid >> 5) & 7;           // warp-uniform
        const int pix = tid & 31;
        const float* ub = s_uh + pix*UH_STRIDE + s*512 + t;   // [zl*32 + c*8]
        float* ex        = s_ex + tid*5;
        const float* exo = s_ex + (tid ^ 256)*5;

        float b0 = 0.f, b1 = 0.f, b2 = 0.f, b3 = 0.f;
        float p[16];

#pragma unroll
        for (int it = 0; it < 3; ++it) {
            float r0 = sigf(b0), r1 = sigf(b1), r2 = sigf(b2), r3 = sigf(b3);
#pragma unroll
            for (int zl = 0; zl < 16; ++zl) {
                const float* u = ub + zl*32;
                p[zl] = u[0]*r0 + u[8]*r1 + u[16]*r2 + u[24]*r3;
            }
            if (s == 0) {                         // psquash over z<16
                float m = 0.f;
#pragma unroll
                for (int zl = 0; zl < 16; ++zl) m = fmaxf(m, fabsf(p[zl]));
                float inv = 1.0f / m;
#pragma unroll
                for (int zl = 0; zl < 16; ++zl) p[zl] *= inv;
            } else {                              // matwo squash over z>=16
                float sq = 0.f;
#pragma unroll
                for (int zl = 0; zl < 16; ++zl) sq = fmaf(p[zl], p[zl], sq);
                float sc = sq / (1.0f + sq) * rsqrtf(sq + 1e-9f);
#pragma unroll
                for (int zl = 0; zl < 16; ++zl) p[zl] *= sc;
            }
            if (it == 2) break;                   // last pass: p holds v

            float q0 = 0.f, q1 = 0.f, q2 = 0.f, q3 = 0.f;
#pragma unroll
            for (int zl = 0; zl < 16; ++zl) {
                const float* u = ub + zl*32;
                q0 = fmaf(u[0],  p[zl], q0);
                q1 = fmaf(u[8],  p[zl], q1);
                q2 = fmaf(u[16], p[zl], q2);
                q3 = fmaf(u[24], p[zl], q3);
            }
            __syncthreads();                      // WAR guard on s_ex
            ex[0] = q0; ex[1] = q1; ex[2] = q2; ex[3] = q3;
            __syncthreads();
            b0 += q0 * exo[0];
            b1 += q1 * exo[1];
            b2 += q2 * exo[2];
            b3 += q3 * exo[3];
        }

        // out[n][t][z][h][w]
        float* ob = out + ((long)(n*8 + t)*32 + s*16)*16384 + h*128 + w0 + pix;
#pragma unroll
        for (int zl = 0; zl < 16; ++zl)
            ob[(long)zl*16384] = p[zl];
    }
}

extern "C" void kernel_launch(void* const* d_in, const int* in_sizes, int n_in,
                              void* d_out, int out_size)
{
    const float* x  = (const float*)d_in[0];
    const float* Wc = (const float*)d_in[1];
    const float* Wp = (const float*)d_in[2];
    const float* Wa = (const float*)d_in[3];
    const float* ba = (const float*)d_in[4];
    float* out = (float*)d_out;

    cudaFuncSetAttribute(caps_kernel,
                         cudaFuncAttributeMaxDynamicSharedMemorySize,
                         SMEM_BYTES);

    dim3 grid(4, 128, 2);   // (w/32, h, n)
    caps_kernel<<<grid, 512, SMEM_BYTES>>>(x, Wc, Wp, Wa, ba, out);
}